// round 15
// baseline (speedup 1.0000x reference)
#include <cuda_runtime.h>
#include <cuda_fp16.h>
#include <math.h>
#include <stdint.h>

#define NB 8
#define NN 8192
#define DD 256
#define NSPLIT 8
#define KT 32

__device__ float d_Spart[NSPLIT * NB * DD * DD];
__device__ float d_S[NB * DD * DD];
__device__ float d_T1[NB * DD * DD];
__device__ float d_P[NB * DD * DD];
__device__ __half d_Mth[NB * DD * DD];
__device__ __half d_Mtl[NB * DD * DD];
__device__ float d_Upart[NSPLIT * NB * DD];
__device__ float d_Wpart[NSPLIT * NB * DD];
__device__ float d_Cpart[NSPLIT * NB];
__device__ float d_kv1[NB * DD];
__device__ float d_kv2[NB * DD];
__device__ float d_r[NB * DD];
__device__ int   g_mask_mode;

// ---------------- helpers ----------------
__global__ void dummy_kernel() {}

__global__ void detect_mask_kernel(const unsigned int* __restrict__ mw) {
    __shared__ int hasByte;
    if (threadIdx.x == 0) hasByte = 0;
    __syncthreads();
    int local = 0;
    for (int i = threadIdx.x; i < 16384; i += blockDim.x) {
        unsigned v = mw[i];
        if (v > 1u && v != 0x3F800000u) local = 1;
    }
    if (local) atomicOr(&hasByte, 1);
    __syncthreads();
    if (threadIdx.x == 0) g_mask_mode = hasByte ? 1 : 0;
}
__device__ __forceinline__ int mask_raw(const void* m, long i, int mode) {
    return (mode == 0) ? (((const unsigned int*)m)[i] != 0u)
                       : (((const unsigned char*)m)[i] != 0);
}
__device__ __forceinline__ void cpa16(void* s, const void* g) {
    unsigned sa = (unsigned)__cvta_generic_to_shared(s);
    asm volatile("cp.async.cg.shared.global [%0], [%1], 16;" :: "r"(sa), "l"(g));
}
#define CPA_COMMIT() asm volatile("cp.async.commit_group;" ::: "memory")
#define CPA_WAIT(n)  asm volatile("cp.async.wait_group %0;" :: "n"(n) : "memory")

__device__ __forceinline__ uint32_t smem_u32(const void* p) {
    uint32_t a;
    asm("{ .reg .u64 t; cvta.to.shared.u64 t, %1; cvt.u32.u64 %0, t; }"
        : "=r"(a) : "l"(p));
    return a;
}
__device__ __forceinline__ void mma16816(float* c, const uint32_t* a, const uint32_t* b) {
    asm volatile("mma.sync.aligned.m16n8k16.row.col.f32.f16.f16.f32 "
        "{%0,%1,%2,%3}, {%4,%5,%6,%7}, {%8,%9}, {%0,%1,%2,%3};"
        : "+f"(c[0]), "+f"(c[1]), "+f"(c[2]), "+f"(c[3])
        : "r"(a[0]), "r"(a[1]), "r"(a[2]), "r"(a[3]), "r"(b[0]), "r"(b[1]));
}
__device__ __forceinline__ void ldsm4t(uint32_t* r, uint32_t a) {
    asm volatile("ldmatrix.sync.aligned.m8n8.x4.trans.shared.b16 {%0,%1,%2,%3}, [%4];"
        : "=r"(r[0]), "=r"(r[1]), "=r"(r[2]), "=r"(r[3]) : "r"(a));
}
__device__ __forceinline__ void split2(float x0, float x1, uint32_t& h, uint32_t& l) {
    __half2 hh = __floats2half2_rn(x0, x1);
    __half2 ll = __floats2half2_rn(x0 - __low2float(hh), x1 - __high2float(hh));
    h = *(uint32_t*)&hh;
    l = *(uint32_t*)&ll;
}
__device__ __forceinline__ uint32_t pack2(float x0, float x1) {
    __half2 hh = __floats2half2_rn(x0, x1);
    return *(uint32_t*)&hh;
}

// ---------------- stage 1: S = key_masked^T @ value (fp16x3, ldmatrix) ----
// CTA 128d x 128e, n-chunk 1024, tile 32 n, double buffered.
// smem stage (32 KB): KH(8K) KL(8K) VH(8K) VL(8K), row n: n*256 + ((u^(n&7))<<4).
__global__ __launch_bounds__(256, 2) void stage1_kernel(
    const float* __restrict__ key, const float* __restrict__ value,
    const void* __restrict__ mask)
{
    __shared__ uint4 smA[2][2048];
    __shared__ float cntsh[KT];

    int t = threadIdx.x, lane = t & 31, wid = t >> 5;
    int b = blockIdx.z >> 3, sp = blockIdx.z & 7;
    int d0 = blockIdx.x * 128, e0 = blockIdx.y * 128;
    int diag = (blockIdx.x == blockIdx.y);
    int zero0 = (d0 == 0 && e0 == 0);
    int mode = g_mask_mode;

    const int chunk = NN / NSPLIT;   // 1024
    long nbase = (long)b * NN + (long)sp * chunk;
    const float* kb = key + nbase * DD;
    const float* vb = value + nbase * DD;

    // producer mapping: row pr (0..31), 8 lanes/row, 16 floats/lane
    int pr = wid * 4 + (lane >> 3);
    int li = lane & 7;
    int pd = li * 16;
    // consumer mapping
    int wn = wid & 3, we = wid >> 2, g = lane >> 2, tg = lane & 3;
    int grp = lane >> 3, l8 = lane & 7;

    float acc[2][8][4];
    #pragma unroll
    for (int mi = 0; mi < 2; mi++)
        #pragma unroll
        for (int ni = 0; ni < 8; ni++)
            #pragma unroll
            for (int j = 0; j < 4; j++) acc[mi][ni][j] = 0.f;
    float colsum = 0.f, cnt = 0.f;

    float4 kf[4], vf[4];
    float mm;
    auto ldt = [&](int kt0) {
        mm = mask_raw(mask, nbase + kt0 + pr, mode) ? 0.f : 1.f;
        const float* kr = kb + (long)(kt0 + pr) * DD + d0 + pd;
        const float* vr = vb + (long)(kt0 + pr) * DD + e0 + pd;
        kf[0] = *(const float4*)kr;       kf[1] = *(const float4*)(kr + 4);
        kf[2] = *(const float4*)(kr + 8); kf[3] = *(const float4*)(kr + 12);
        vf[0] = *(const float4*)vr;       vf[1] = *(const float4*)(vr + 4);
        vf[2] = *(const float4*)(vr + 8); vf[3] = *(const float4*)(vr + 12);
    };

    const int ntiles = chunk / KT;   // 32
    ldt(0);

    for (int i = 0; i < ntiles; i++) {
        int s = i & 1;
        char* smb = (char*)smA[s];
        {   // split + row-major STS.128 (two 16B units per lane per matrix)
            int o0 = pr * 256 + (((li * 2) ^ (pr & 7)) << 4);
            int o1 = pr * 256 + (((li * 2 + 1) ^ (pr & 7)) << 4);
            uint4 h, l;
            split2(kf[0].x * mm, kf[0].y * mm, h.x, l.x);
            split2(kf[0].z * mm, kf[0].w * mm, h.y, l.y);
            split2(kf[1].x * mm, kf[1].y * mm, h.z, l.z);
            split2(kf[1].z * mm, kf[1].w * mm, h.w, l.w);
            *(uint4*)(smb + o0) = h; *(uint4*)(smb + 8192 + o0) = l;
            split2(kf[2].x * mm, kf[2].y * mm, h.x, l.x);
            split2(kf[2].z * mm, kf[2].w * mm, h.y, l.y);
            split2(kf[3].x * mm, kf[3].y * mm, h.z, l.z);
            split2(kf[3].z * mm, kf[3].w * mm, h.w, l.w);
            *(uint4*)(smb + o1) = h; *(uint4*)(smb + 8192 + o1) = l;
            split2(vf[0].x, vf[0].y, h.x, l.x);
            split2(vf[0].z, vf[0].w, h.y, l.y);
            split2(vf[1].x, vf[1].y, h.z, l.z);
            split2(vf[1].z, vf[1].w, h.w, l.w);
            *(uint4*)(smb + 16384 + o0) = h; *(uint4*)(smb + 24576 + o0) = l;
            split2(vf[2].x, vf[2].y, h.x, l.x);
            split2(vf[2].z, vf[2].w, h.y, l.y);
            split2(vf[3].x, vf[3].y, h.z, l.z);
            split2(vf[3].z, vf[3].w, h.w, l.w);
            *(uint4*)(smb + 16384 + o1) = h; *(uint4*)(smb + 24576 + o1) = l;
        }
        __syncthreads();
        if (i + 1 < ntiles) ldt((i + 1) * KT);

        uint32_t bbm = smem_u32(smA[s]);
        #pragma unroll
        for (int ks = 0; ks < 2; ks++) {
            int kb16 = ks * 16;
            uint32_t aH[2][4], aL[2][4];
            int nA = kb16 + ((grp >> 1) << 3) + l8;
            #pragma unroll
            for (int mi = 0; mi < 2; mi++) {
                int uA = wn * 4 + mi * 2 + (grp & 1);
                uint32_t ad = bbm + nA * 256 + ((uA ^ (nA & 7)) << 4);
                ldsm4t(aH[mi], ad);
                ldsm4t(aL[mi], ad + 8192);
            }
            int nB = kb16 + ((grp & 1) << 3) + l8;
            #pragma unroll
            for (int nf = 0; nf < 4; nf++) {
                int uB = we * 8 + nf * 2 + (grp >> 1);
                uint32_t bd = bbm + 16384 + nB * 256 + ((uB ^ (nB & 7)) << 4);
                uint32_t bh4[4], bl4[4];
                ldsm4t(bh4, bd);
                ldsm4t(bl4, bd + 8192);
                uint32_t bh0[2] = {bh4[0], bh4[1]}, bh1[2] = {bh4[2], bh4[3]};
                uint32_t bl0[2] = {bl4[0], bl4[1]}, bl1[2] = {bl4[2], bl4[3]};
                #pragma unroll
                for (int mi = 0; mi < 2; mi++) {
                    mma16816(acc[mi][nf * 2], aH[mi], bh0);
                    mma16816(acc[mi][nf * 2], aH[mi], bl0);
                    mma16816(acc[mi][nf * 2], aL[mi], bh0);
                    mma16816(acc[mi][nf * 2 + 1], aH[mi], bh1);
                    mma16816(acc[mi][nf * 2 + 1], aH[mi], bl1);
                    mma16816(acc[mi][nf * 2 + 1], aL[mi], bh1);
                }
            }
        }
        if (diag) {   // column sums (hi+lo) for u / w
            int cc = t & 127;
            int u = cc >> 3, bo = (cc & 7) * 2;
            const char* P = (t < 128) ? smb : smb + 16384;
            float sa = 0.f;
            #pragma unroll
            for (int r = 0; r < KT; r++) {
                int o = r * 256 + ((u ^ (r & 7)) << 4) + bo;
                sa += __half2float(*(const __half*)(P + o))
                    + __half2float(*(const __half*)(P + 8192 + o));
            }
            colsum += sa;
        }
        if (zero0 && t < KT)
            cnt += mask_raw(mask, nbase + (long)i * KT + t, mode) ? 0.f : 1.f;
    }

    float* outp = d_Spart + ((long)(sp * NB + b) << 16);
    #pragma unroll
    for (int mi = 0; mi < 2; mi++) {
        int d = d0 + wn * 32 + mi * 16 + g;
        #pragma unroll
        for (int ni = 0; ni < 8; ni++) {
            int e = e0 + we * 64 + ni * 8 + 2 * tg;
            float2 v;
            v.x = acc[mi][ni][0]; v.y = acc[mi][ni][1];
            *(float2*)&outp[(long)d * DD + e] = v;
            v.x = acc[mi][ni][2]; v.y = acc[mi][ni][3];
            *(float2*)&outp[(long)(d + 8) * DD + e] = v;
        }
    }
    if (diag) {
        int cc = t & 127;
        if (t < 128) d_Upart[(sp * NB + b) * DD + d0 + cc] = colsum;
        else         d_Wpart[(sp * NB + b) * DD + e0 + cc] = colsum;
    }
    if (zero0) {
        if (t < KT) cntsh[t] = cnt;
        __syncthreads();
        if (t == 0) {
            float s = 0.f;
            #pragma unroll
            for (int k = 0; k < KT; k++) s += cntsh[k];
            d_Cpart[sp * NB + b] = s;
        }
    }
}

// vectorized partial reduce
__global__ void s_reduce_kernel() {
    long i = ((long)blockIdx.x * 256 + threadIdx.x) * 4;
    int b = (int)(i >> 16);
    int j = (int)(i & 65535);
    float4 s = make_float4(0.f, 0.f, 0.f, 0.f);
    #pragma unroll
    for (int sp = 0; sp < NSPLIT; sp++) {
        float4 v = *(const float4*)&d_Spart[((long)(sp * NB + b) << 16) + j];
        s.x += v.x; s.y += v.y; s.z += v.z; s.w += v.w;
    }
    *(float4*)&d_S[((long)b << 16) + j] = s;
}

// fused uvw reduce + kv matvecs
__global__ __launch_bounds__(256) void uvwkv_kernel(
    const float* __restrict__ Wk, const float* __restrict__ Wv,
    const float* __restrict__ bv)
{
    __shared__ float su[DD], sw[DD];
    __shared__ float scc;
    int b = blockIdx.x, dblk = blockIdx.y;
    int t = threadIdx.x, lane = t & 31, wid = t >> 5;

    float a1 = 0.f, a2 = 0.f;
    #pragma unroll
    for (int sp = 0; sp < NSPLIT; sp++) {
        a1 += d_Upart[(sp * NB + b) * DD + t];
        a2 += d_Wpart[(sp * NB + b) * DD + t];
    }
    su[t] = a1; sw[t] = a2;
    if (t == 0) {
        float c = 0.f;
        #pragma unroll
        for (int sp = 0; sp < NSPLIT; sp++) c += d_Cpart[sp * NB + b];
        scc = c;
    }
    __syncthreads();

    int sub = lane >> 3, li = lane & 7;
    int d = dblk * 32 + wid * 4 + sub;
    const float* wk = Wk + (long)d * DD;
    const float* wv = Wv + (long)d * DD;
    float s1 = 0.f, s2 = 0.f;
    #pragma unroll
    for (int ii = 0; ii < 8; ii++) {
        int c4 = (li + ii * 8) * 4;
        float4 wa = *(const float4*)(wk + c4);
        float4 ua = *(const float4*)(su + c4);
        float4 wb = *(const float4*)(wv + c4);
        float4 va = *(const float4*)(sw + c4);
        s1 += wa.x * ua.x + wa.y * ua.y + wa.z * ua.z + wa.w * ua.w;
        s2 += wb.x * va.x + wb.y * va.y + wb.z * va.z + wb.w * va.w;
    }
    #pragma unroll
    for (int m = 4; m; m >>= 1) {
        s1 += __shfl_xor_sync(0xFFFFFFFFu, s1, m);
        s2 += __shfl_xor_sync(0xFFFFFFFFu, s2, m);
    }
    if (li == 0) {
        d_kv1[b * DD + d] = s1;
        d_kv2[b * DD + d] = s2 + scc * bv[d];
    }
}

// ---------------- small batched GEMM ----------------
template<bool TA, bool TB, bool EPI, bool SPL>
__global__ __launch_bounds__(128) void sgemm_k(
    const float* __restrict__ A, long sA,
    const float* __restrict__ B, long sB,
    float* __restrict__ C, __half* __restrict__ Ch, __half* __restrict__ Cl,
    const float* __restrict__ x1, int sx1,
    const float* __restrict__ y1, int sy1,
    const float* __restrict__ x2, int sx2,
    const float* __restrict__ y2, int sy2,
    float scale)
{
    __shared__ float As[16][36];
    __shared__ float Bs[16][68];
    int t = threadIdx.x;
    int b = blockIdx.z;
    int d0 = blockIdx.x * 32, e0 = blockIdx.y * 64;
    const float* Ab = A + (long)b * sA;
    const float* Bb = B + (long)b * sB;
    int td = t & 7, te = t >> 3;

    float acc[4][4];
    #pragma unroll
    for (int r = 0; r < 4; r++)
        #pragma unroll
        for (int c = 0; c < 4; c++) acc[r][c] = 0.f;

    for (int kt = 0; kt < DD; kt += 16) {
        if (TA) {
            int row = t >> 3, col = (t & 7) * 4;
            *(float4*)&As[row][col] = *(const float4*)&Ab[(long)(kt + row) * DD + d0 + col];
        } else {
            int row = t >> 2, col = (t & 3) * 4;
            float4 v = *(const float4*)&Ab[(long)(d0 + row) * DD + kt + col];
            As[col + 0][row] = v.x; As[col + 1][row] = v.y;
            As[col + 2][row] = v.z; As[col + 3][row] = v.w;
        }
        #pragma unroll
        for (int h = 0; h < 2; h++) {
            int idx = t * 4 + h * 512;
            if (TB) {
                int row = idx >> 4, col = idx & 15;
                float4 v = *(const float4*)&Bb[(long)(e0 + row) * DD + kt + col];
                Bs[col + 0][row] = v.x; Bs[col + 1][row] = v.y;
                Bs[col + 2][row] = v.z; Bs[col + 3][row] = v.w;
            } else {
                int row = idx >> 6, col = idx & 63;
                *(float4*)&Bs[row][col] = *(const float4*)&Bb[(long)(kt + row) * DD + e0 + col];
            }
        }
        __syncthreads();
        #pragma unroll
        for (int k = 0; k < 16; k++) {
            float4 a = *(const float4*)&As[k][td * 4];
            float4 bb = *(const float4*)&Bs[k][te * 4];
            float av[4] = {a.x, a.y, a.z, a.w};
            float bv2[4] = {bb.x, bb.y, bb.z, bb.w};
            #pragma unroll
            for (int r = 0; r < 4; r++)
                #pragma unroll
                for (int c = 0; c < 4; c++)
                    acc[r][c] = fmaf(av[r], bv2[c], acc[r][c]);
        }
        __syncthreads();
    }

    #pragma unroll
    for (int r = 0; r < 4; r++) {
        int d = d0 + td * 4 + r;
        #pragma unroll
        for (int c = 0; c < 4; c++) {
            int e = e0 + te * 4 + c;
            float v = acc[r][c];
            if (EPI)
                v = (v + x1[b * sx1 + d] * y1[b * sy1 + e]
                       + x2[b * sx2 + d] * y2[b * sy2 + e]) * scale;
            long offo = ((long)b << 16) + (long)d * DD + e;
            if (SPL) {
                __half h = __float2half_rn(v);
                Ch[offo] = h;
                Cl[offo] = __float2half_rn(v - __half2float(h));
            } else {
                C[offo] = v;
            }
        }
    }
}

// ---------------- softmax + fused r = bq^T aw ----------------
__global__ void softmax_kernel(const float* __restrict__ bq) {
    int b = blockIdx.x, ec = blockIdx.y;
    int tx = threadIdx.x, ty = threadIdx.y;
    float* Pb = d_P + ((long)b << 16);
    int e = ec * 64 + tx;
    __shared__ float red[4][64];

    float mx = -3.4e38f;
    for (int d = ty; d < DD; d += 4) mx = fmaxf(mx, Pb[(long)d * DD + e]);
    red[ty][tx] = mx;
    __syncthreads();
    mx = fmaxf(fmaxf(red[0][tx], red[1][tx]), fmaxf(red[2][tx], red[3][tx]));
    __syncthreads();
    float s = 0.f;
    for (int d = ty; d < DD; d += 4) {
        float ev = expf(Pb[(long)d * DD + e] - mx);
        Pb[(long)d * DD + e] = ev;
        s += ev;
    }
    red[ty][tx] = s;
    __syncthreads();
    float inv = 1.0f / (red[0][tx] + red[1][tx] + red[2][tx] + red[3][tx]);
    __syncthreads();
    float rr = 0.f;
    for (int d = ty; d < DD; d += 4) {
        float val = Pb[(long)d * DD + e] * inv;
        Pb[(long)d * DD + e] = val;
        rr = fmaf(bq[d], val, rr);
    }
    red[ty][tx] = rr;
    __syncthreads();
    if (ty == 0)
        d_r[b * DD + e] = red[0][tx] + red[1][tx] + red[2][tx] + red[3][tx];
}

// ---------------- stage 3: out = q @ M + r (fp16 2-term mma) ---------------
#define S3_STRIDE 1920
#define S3_SMEM (2 * S3_STRIDE * 16)
__device__ __forceinline__ int offA32(int r, int kp) {
    return (r * 5 + ((kp >> 2) ^ (r & 3))) * 4 + (kp & 3);
}

__global__ __launch_bounds__(256, 2) void stage3_kernel(
    const float* __restrict__ query, float* __restrict__ out)
{
    extern __shared__ uint4 sm[];
    __shared__ float rsh[DD];
    int t = threadIdx.x, lane = t & 31, wid = t >> 5;
    int b = blockIdx.z;
    long n0 = (long)blockIdx.x * 128;
    int e0 = blockIdx.y * 128;
    const float* qb = query + ((long)b * NN + n0) * DD;
    const __half* Bhp = d_Mth + ((long)b << 16) + (long)e0 * DD;
    const __half* Blp = d_Mtl + ((long)b << 16) + (long)e0 * DD;
    if (t < DD) rsh[t] = d_r[b * DD + t];

    int wn = wid & 3, we = wid >> 2, g = lane >> 2, tg = lane & 3;

    auto issueB = [&](int c, int s) {
        uint4* BH = sm + s * S3_STRIDE + 640;
        uint4* BL = BH + 640;
        #pragma unroll
        for (int a = 0; a < 2; a++) {
            int idx = t + a * 256, e = idx >> 2, u = idx & 3;
            int i16 = e * 5 + (u ^ (e & 3));
            cpa16(&BH[i16], Bhp + (long)e * DD + c * 32 + u * 8);
            cpa16(&BL[i16], Blp + (long)e * DD + c * 32 + u * 8);
        }
        CPA_COMMIT();
    };

    float4 pa[2], pb[2];
    auto ldtA = [&](int c) {
        #pragma unroll
        for (int a = 0; a < 2; a++) {
            int idx = t + a * 256, row = idx >> 2, u = idx & 3;
            const float* src = qb + (long)row * DD + c * 32 + u * 8;
            pa[a] = *(const float4*)src;
            pb[a] = *(const float4*)(src + 4);
        }
    };
    auto stsA = [&](int s) {
        uint4* AH = sm + s * S3_STRIDE;
        #pragma unroll
        for (int a = 0; a < 2; a++) {
            int idx = t + a * 256, row = idx >> 2, u = idx & 3;
            uint4 h;
            h.x = pack2(pa[a].x, pa[a].y); h.y = pack2(pa[a].z, pa[a].w);
            h.z = pack2(pb[a].x, pb[a].y); h.w = pack2(pb[a].z, pb[a].w);
            AH[row * 5 + (u ^ (row & 3))] = h;
        }
    };

    float acc[2][8][4];
    #pragma unroll
    for (int mi = 0; mi < 2; mi++)
        #pragma unroll
        for (int ni = 0; ni < 8; ni++)
            #pragma unroll
            for (int j = 0; j < 4; j++) acc[mi][ni][j] = 0.f;

    ldtA(0);
    issueB(0, 0);

    for (int c = 0; c < 8; c++) {
        int s = c & 1;
        stsA(s);
        if (c < 7) {
            ldtA(c + 1);
            issueB(c + 1, 1 - s);
            CPA_WAIT(1);
        } else {
            CPA_WAIT(0);
        }
        __syncthreads();

        const uint32_t* AH = (const uint32_t*)(sm + s * S3_STRIDE);
        const uint32_t* BH = AH + 2560;
        const uint32_t* BL = AH + 5120;
        #pragma unroll
        for (int j = 0; j < 2; j++) {
            int kp0 = j * 8 + tg, kp1 = kp0 + 4;
            uint32_t ah[2][4];
            #pragma unroll
            for (int mi = 0; mi < 2; mi++) {
                int r = wn * 32 + mi * 16 + g;
                ah[mi][0] = AH[offA32(r, kp0)];     ah[mi][1] = AH[offA32(r + 8, kp0)];
                ah[mi][2] = AH[offA32(r, kp1)];     ah[mi][3] = AH[offA32(r + 8, kp1)];
            }
            #pragma unroll
            for (int ni = 0; ni < 8; ni++) {
                int e = we * 64 + ni * 8 + g;
                uint32_t bhf[2] = {BH[offA32(e, kp0)], BH[offA32(e, kp1)]};
                uint32_t blf[2] = {BL[offA32(e, kp0)], BL[offA32(e, kp1)]};
                #pragma unroll
                for (int mi = 0; mi < 2; mi++) {
                    mma16816(acc[mi][ni], ah[mi], bhf);
                    mma16816(acc[mi][ni], ah[mi], blf);
                }
            }
        }
        __syncthreads();
    }

    #pragma unroll
    for (int mi = 0; mi < 2; mi++) {
        long nr = n0 + wn * 32 + mi * 16;
        #pragma unroll
        for (int ni = 0; ni < 8; ni++) {
            int eg = e0 + we * 64 + ni * 8 + tg * 2;
            float2 v0, v1;
            v0.x = acc[mi][ni][0] + rsh[eg];
            v0.y = acc[mi][ni][1] + rsh[eg + 1];
            v1.x = acc[mi][ni][2] + rsh[eg];
            v1.y = acc[mi][ni][3] + rsh[eg + 1];
            *(float2*)(out + ((long)b * NN + nr + g) * DD + eg) = v0;
            *(float2*)(out + ((long)b * NN + nr + g + 8) * DD + eg) = v1;
        }
    }
}

// ---------------------------------------------------------------------------
extern "C" void kernel_launch(void* const* d_in, const int* in_sizes, int n_in,
                              void* d_out, int out_size)
{
    const float* query = (const float*)d_in[0];
    const float* key   = (const float*)d_in[1];
    const float* value = (const float*)d_in[2];
    const void*  mask  = d_in[3];
    int wo = (n_in >= 11 && in_sizes[4] == 1) ? 5 : 4;
    const float* Wq = (const float*)d_in[wo + 0];
    const float* bq = (const float*)d_in[wo + 1];
    const float* Wk = (const float*)d_in[wo + 2];
    const float* bk = (const float*)d_in[wo + 3];
    const float* Wv = (const float*)d_in[wo + 4];
    const float* bv = (const float*)d_in[wo + 5];
    float* out = (float*)d_out;

    float *pS, *pT1, *pP, *pkv1, *pkv2;
    __half *pMth, *pMtl;
    cudaGetSymbolAddress((void**)&pS, d_S);
    cudaGetSymbolAddress((void**)&pT1, d_T1);
    cudaGetSymbolAddress((void**)&pP, d_P);
    cudaGetSymbolAddress((void**)&pMth, d_Mth);
    cudaGetSymbolAddress((void**)&pMtl, d_Mtl);
    cudaGetSymbolAddress((void**)&pkv1, d_kv1);
    cudaGetSymbolAddress((void**)&pkv2, d_kv2);

    cudaFuncSetAttribute(stage3_kernel,
                         cudaFuncAttributeMaxDynamicSharedMemorySize, S3_SMEM);

    const float inv_sqrt8 = 0.35355339059327373f;

    detect_mask_kernel<<<1, 256>>>((const unsigned int*)mask);   // launch 0
    dummy_kernel<<<1, 32>>>();                                   // launch 1
    dummy_kernel<<<1, 32>>>();                                   // launch 2
    stage1_kernel<<<dim3(2, 2, NB * NSPLIT), 256>>>(key, value, mask);  // launch 3 (profiled)
    s_reduce_kernel<<<NB * DD * DD / 1024, 256>>>();
    uvwkv_kernel<<<dim3(NB, 8), 256>>>(Wk, Wv, bv);
    // T1 = Wk @ S
    sgemm_k<false, false, false, false><<<dim3(8, 4, NB), 128>>>(
        Wk, 0, pS, (long)DD * DD, pT1, nullptr, nullptr,
        nullptr, 0, nullptr, 0, nullptr, 0, nullptr, 0, 1.0f);
    // P = (T1 @ Wv^T + kv1*bv^T + bk*kv2^T) / sqrt(8)
    sgemm_k<false, true, true, false><<<dim3(8, 4, NB), 128>>>(
        pT1, (long)DD * DD, Wv, 0, pP, nullptr, nullptr,
        pkv1, DD, bv, 0, bk, 0, pkv2, DD, inv_sqrt8);
    softmax_kernel<<<dim3(NB, 4), dim3(64, 4)>>>(bq);
    // Mt[e][d] = (aw^T @ Wq), fp16 hi/lo split epilogue
    sgemm_k<true, false, false, true><<<dim3(8, 4, NB), 128>>>(
        pP, (long)DD * DD, Wq, 0, nullptr, pMth, pMtl,
        nullptr, 0, nullptr, 0, nullptr, 0, nullptr, 0, 1.0f);
    stage3_kernel<<<dim3(64, 2, NB), 256, S3_SMEM>>>(query, out);
}

// round 16
// speedup vs baseline: 1.1025x; 1.1025x over previous
#include <cuda_runtime.h>
#include <cuda_fp16.h>
#include <math.h>
#include <stdint.h>

#define NB 8
#define NN 8192
#define DD 256
#define NSPLIT 8
#define KT 32
#define S1P 136

__device__ float d_Spart[NSPLIT * NB * DD * DD];
__device__ float d_S[NB * DD * DD];
__device__ float d_T1[NB * DD * DD];
__device__ float d_P[NB * DD * DD];
__device__ __half d_Mth[NB * DD * DD];
__device__ __half d_Mtl[NB * DD * DD];
__device__ float d_Upart[NSPLIT * NB * DD];
__device__ float d_Wpart[NSPLIT * NB * DD];
__device__ float d_Cpart[NSPLIT * NB];
__device__ float d_kv1[NB * DD];
__device__ float d_kv2[NB * DD];
__device__ float d_r[NB * DD];
__device__ int   g_mask_mode;

// ---------------- helpers ----------------
__global__ void dummy_kernel() {}

__global__ void detect_mask_kernel(const unsigned int* __restrict__ mw) {
    __shared__ int hasByte;
    if (threadIdx.x == 0) hasByte = 0;
    __syncthreads();
    int local = 0;
    for (int i = threadIdx.x; i < 16384; i += blockDim.x) {
        unsigned v = mw[i];
        if (v > 1u && v != 0x3F800000u) local = 1;
    }
    if (local) atomicOr(&hasByte, 1);
    __syncthreads();
    if (threadIdx.x == 0) g_mask_mode = hasByte ? 1 : 0;
}
__device__ __forceinline__ int mask_raw(const void* m, long i, int mode) {
    return (mode == 0) ? (((const unsigned int*)m)[i] != 0u)
                       : (((const unsigned char*)m)[i] != 0);
}
__device__ __forceinline__ void cpa16(void* s, const void* g) {
    unsigned sa = (unsigned)__cvta_generic_to_shared(s);
    asm volatile("cp.async.cg.shared.global [%0], [%1], 16;" :: "r"(sa), "l"(g));
}
#define CPA_COMMIT() asm volatile("cp.async.commit_group;" ::: "memory")
#define CPA_WAIT(n)  asm volatile("cp.async.wait_group %0;" :: "n"(n) : "memory")

__device__ __forceinline__ void mma16816(float* c, const uint32_t* a, const uint32_t* b) {
    asm volatile("mma.sync.aligned.m16n8k16.row.col.f32.f16.f16.f32 "
        "{%0,%1,%2,%3}, {%4,%5,%6,%7}, {%8,%9}, {%0,%1,%2,%3};"
        : "+f"(c[0]), "+f"(c[1]), "+f"(c[2]), "+f"(c[3])
        : "r"(a[0]), "r"(a[1]), "r"(a[2]), "r"(a[3]), "r"(b[0]), "r"(b[1]));
}
__device__ __forceinline__ void split2(float x0, float x1, uint32_t& h, uint32_t& l) {
    __half2 hh = __floats2half2_rn(x0, x1);
    __half2 ll = __floats2half2_rn(x0 - __low2float(hh), x1 - __high2float(hh));
    h = *(uint32_t*)&hh;
    l = *(uint32_t*)&ll;
}
__device__ __forceinline__ uint32_t pack2(float x0, float x1) {
    __half2 hh = __floats2half2_rn(x0, x1);
    return *(uint32_t*)&hh;
}

// ---------------- stage 1: S = key_masked^T @ value (fp16x3 mma) ----------
// CTA 128d x 128e, n-chunk 1024, tile KT=32 n (16 pairs), double buffered.
// Colsums (u, w) accumulated in producer registers; smem-reduced at end.
__global__ __launch_bounds__(256, 2) void stage1_kernel(
    const float* __restrict__ key, const float* __restrict__ value,
    const void* __restrict__ mask)
{
    __shared__ uint32_t Ah[2][16 * S1P], Al[2][16 * S1P];
    __shared__ uint32_t Bh[2][16 * S1P], Bl[2][16 * S1P];
    __shared__ float redA[8 * 128];
    __shared__ float redB[8 * 128];
    __shared__ float cntsh[KT];

    int t = threadIdx.x, lane = t & 31, wid = t >> 5;
    int b = blockIdx.z >> 3, sp = blockIdx.z & 7;
    int d0 = blockIdx.x * 128, e0 = blockIdx.y * 128;
    int diag = (blockIdx.x == blockIdx.y);
    int zero0 = (d0 == 0 && e0 == 0);
    int mode = g_mask_mode;

    const int chunk = NN / NSPLIT;   // 1024
    long nbase = (long)b * NN + (long)sp * chunk;
    const float* kb = key + nbase * DD;
    const float* vb = value + nbase * DD;

    int p0 = 2 * wid, p1 = 2 * wid + 1;
    int dq = lane * 4;
    int wn = wid & 3, we = wid >> 2, g = lane >> 2, tg = lane & 3;

    float acc[2][8][4];
    #pragma unroll
    for (int mi = 0; mi < 2; mi++)
        #pragma unroll
        for (int ni = 0; ni < 8; ni++)
            #pragma unroll
            for (int j = 0; j < 4; j++) acc[mi][ni][j] = 0.f;
    float csA[4] = {0.f, 0.f, 0.f, 0.f};
    float csB[4] = {0.f, 0.f, 0.f, 0.f};
    float cnt = 0.f;

    float4 k0, k1, k2, k3, v0, v1, v2, v3;
    float m0, m1, m2, m3;
    auto ldt = [&](int kt0) {
        long nr = nbase + kt0 + 4 * wid;
        m0 = mask_raw(mask, nr + 0, mode) ? 0.f : 1.f;
        m1 = mask_raw(mask, nr + 1, mode) ? 0.f : 1.f;
        m2 = mask_raw(mask, nr + 2, mode) ? 0.f : 1.f;
        m3 = mask_raw(mask, nr + 3, mode) ? 0.f : 1.f;
        const float* kr = kb + (long)(kt0 + 4 * wid) * DD + d0 + dq;
        const float* vr = vb + (long)(kt0 + 4 * wid) * DD + e0 + dq;
        k0 = *(const float4*)kr;            k1 = *(const float4*)(kr + DD);
        k2 = *(const float4*)(kr + 2 * DD); k3 = *(const float4*)(kr + 3 * DD);
        v0 = *(const float4*)vr;            v1 = *(const float4*)(vr + DD);
        v2 = *(const float4*)(vr + 2 * DD); v3 = *(const float4*)(vr + 3 * DD);
    };

    const int ntiles = chunk / KT;   // 32
    ldt(0);

    for (int i = 0; i < ntiles; i++) {
        int s = i & 1;
        {
            float a0[4] = {k0.x * m0, k0.y * m0, k0.z * m0, k0.w * m0};
            float a1[4] = {k1.x * m1, k1.y * m1, k1.z * m1, k1.w * m1};
            float a2[4] = {k2.x * m2, k2.y * m2, k2.z * m2, k2.w * m2};
            float a3[4] = {k3.x * m3, k3.y * m3, k3.z * m3, k3.w * m3};
            float b0[4] = {v0.x, v0.y, v0.z, v0.w};
            float b1[4] = {v1.x, v1.y, v1.z, v1.w};
            float b2[4] = {v2.x, v2.y, v2.z, v2.w};
            float b3[4] = {v3.x, v3.y, v3.z, v3.w};
            if (diag) {
                #pragma unroll
                for (int j = 0; j < 4; j++) {
                    csA[j] += a0[j] + a1[j] + a2[j] + a3[j];
                    csB[j] += m0 * b0[j] + m1 * b1[j] + m2 * b2[j] + m3 * b3[j];
                }
            }
            uint4 h0, l0, h1, l1;
            split2(a0[0], a1[0], h0.x, l0.x); split2(a0[1], a1[1], h0.y, l0.y);
            split2(a0[2], a1[2], h0.z, l0.z); split2(a0[3], a1[3], h0.w, l0.w);
            split2(a2[0], a3[0], h1.x, l1.x); split2(a2[1], a3[1], h1.y, l1.y);
            split2(a2[2], a3[2], h1.z, l1.z); split2(a2[3], a3[3], h1.w, l1.w);
            *(uint4*)&Ah[s][p0 * S1P + dq] = h0; *(uint4*)&Al[s][p0 * S1P + dq] = l0;
            *(uint4*)&Ah[s][p1 * S1P + dq] = h1; *(uint4*)&Al[s][p1 * S1P + dq] = l1;
            split2(b0[0], b1[0], h0.x, l0.x); split2(b0[1], b1[1], h0.y, l0.y);
            split2(b0[2], b1[2], h0.z, l0.z); split2(b0[3], b1[3], h0.w, l0.w);
            split2(b2[0], b3[0], h1.x, l1.x); split2(b2[1], b3[1], h1.y, l1.y);
            split2(b2[2], b3[2], h1.z, l1.z); split2(b2[3], b3[3], h1.w, l1.w);
            *(uint4*)&Bh[s][p0 * S1P + dq] = h0; *(uint4*)&Bl[s][p0 * S1P + dq] = l0;
            *(uint4*)&Bh[s][p1 * S1P + dq] = h1; *(uint4*)&Bl[s][p1 * S1P + dq] = l1;
        }
        __syncthreads();
        if (i + 1 < ntiles) ldt((i + 1) * KT);

        #pragma unroll
        for (int ks = 0; ks < 2; ks++) {
            int q0 = ks * 8 + tg, q1 = ks * 8 + tg + 4;
            uint32_t ah[2][4], al[2][4];
            #pragma unroll
            for (int mi = 0; mi < 2; mi++) {
                int r = wn * 32 + mi * 16 + g;
                ah[mi][0] = Ah[s][q0 * S1P + r]; ah[mi][1] = Ah[s][q0 * S1P + r + 8];
                ah[mi][2] = Ah[s][q1 * S1P + r]; ah[mi][3] = Ah[s][q1 * S1P + r + 8];
                al[mi][0] = Al[s][q0 * S1P + r]; al[mi][1] = Al[s][q0 * S1P + r + 8];
                al[mi][2] = Al[s][q1 * S1P + r]; al[mi][3] = Al[s][q1 * S1P + r + 8];
            }
            #pragma unroll
            for (int ni = 0; ni < 8; ni++) {
                int e = we * 64 + ni * 8 + g;
                uint32_t bhf[2] = {Bh[s][q0 * S1P + e], Bh[s][q1 * S1P + e]};
                uint32_t blf[2] = {Bl[s][q0 * S1P + e], Bl[s][q1 * S1P + e]};
                #pragma unroll
                for (int mi = 0; mi < 2; mi++) {
                    mma16816(acc[mi][ni], ah[mi], bhf);
                    mma16816(acc[mi][ni], ah[mi], blf);
                    mma16816(acc[mi][ni], al[mi], bhf);
                }
            }
        }
        if (zero0 && t < KT)
            cnt += mask_raw(mask, nbase + (long)i * KT + t, mode) ? 0.f : 1.f;
    }

    float* outp = d_Spart + ((long)(sp * NB + b) << 16);
    #pragma unroll
    for (int mi = 0; mi < 2; mi++) {
        int d = d0 + wn * 32 + mi * 16 + g;
        #pragma unroll
        for (int ni = 0; ni < 8; ni++) {
            int e = e0 + we * 64 + ni * 8 + 2 * tg;
            float2 v;
            v.x = acc[mi][ni][0]; v.y = acc[mi][ni][1];
            *(float2*)&outp[(long)d * DD + e] = v;
            v.x = acc[mi][ni][2]; v.y = acc[mi][ni][3];
            *(float2*)&outp[(long)(d + 8) * DD + e] = v;
        }
    }
    if (diag) {   // cross-warp reduce of register colsums
        #pragma unroll
        for (int j = 0; j < 4; j++) {
            redA[wid * 128 + dq + j] = csA[j];
            redB[wid * 128 + dq + j] = csB[j];
        }
        __syncthreads();
        if (t < 128) {
            float s = 0.f;
            #pragma unroll
            for (int w2 = 0; w2 < 8; w2++) s += redA[w2 * 128 + t];
            d_Upart[(sp * NB + b) * DD + d0 + t] = s;
        } else {
            int t2 = t - 128;
            float s = 0.f;
            #pragma unroll
            for (int w2 = 0; w2 < 8; w2++) s += redB[w2 * 128 + t2];
            d_Wpart[(sp * NB + b) * DD + e0 + t2] = s;
        }
    }
    if (zero0) {
        if (t < KT) cntsh[t] = cnt;
        __syncthreads();
        if (t == 0) {
            float s = 0.f;
            #pragma unroll
            for (int k = 0; k < KT; k++) s += cntsh[k];
            d_Cpart[sp * NB + b] = s;
        }
    }
}

// vectorized partial reduce
__global__ void s_reduce_kernel() {
    long i = ((long)blockIdx.x * 256 + threadIdx.x) * 4;
    int b = (int)(i >> 16);
    int j = (int)(i & 65535);
    float4 s = make_float4(0.f, 0.f, 0.f, 0.f);
    #pragma unroll
    for (int sp = 0; sp < NSPLIT; sp++) {
        float4 v = *(const float4*)&d_Spart[((long)(sp * NB + b) << 16) + j];
        s.x += v.x; s.y += v.y; s.z += v.z; s.w += v.w;
    }
    *(float4*)&d_S[((long)b << 16) + j] = s;
}

// fused uvw reduce + kv matvecs
__global__ __launch_bounds__(256) void uvwkv_kernel(
    const float* __restrict__ Wk, const float* __restrict__ Wv,
    const float* __restrict__ bv)
{
    __shared__ float su[DD], sw[DD];
    __shared__ float scc;
    int b = blockIdx.x, dblk = blockIdx.y;
    int t = threadIdx.x, lane = t & 31, wid = t >> 5;

    float a1 = 0.f, a2 = 0.f;
    #pragma unroll
    for (int sp = 0; sp < NSPLIT; sp++) {
        a1 += d_Upart[(sp * NB + b) * DD + t];
        a2 += d_Wpart[(sp * NB + b) * DD + t];
    }
    su[t] = a1; sw[t] = a2;
    if (t == 0) {
        float c = 0.f;
        #pragma unroll
        for (int sp = 0; sp < NSPLIT; sp++) c += d_Cpart[sp * NB + b];
        scc = c;
    }
    __syncthreads();

    int sub = lane >> 3, li = lane & 7;
    int d = dblk * 32 + wid * 4 + sub;
    const float* wk = Wk + (long)d * DD;
    const float* wv = Wv + (long)d * DD;
    float s1 = 0.f, s2 = 0.f;
    #pragma unroll
    for (int ii = 0; ii < 8; ii++) {
        int c4 = (li + ii * 8) * 4;
        float4 wa = *(const float4*)(wk + c4);
        float4 ua = *(const float4*)(su + c4);
        float4 wb = *(const float4*)(wv + c4);
        float4 va = *(const float4*)(sw + c4);
        s1 += wa.x * ua.x + wa.y * ua.y + wa.z * ua.z + wa.w * ua.w;
        s2 += wb.x * va.x + wb.y * va.y + wb.z * va.z + wb.w * va.w;
    }
    #pragma unroll
    for (int m = 4; m; m >>= 1) {
        s1 += __shfl_xor_sync(0xFFFFFFFFu, s1, m);
        s2 += __shfl_xor_sync(0xFFFFFFFFu, s2, m);
    }
    if (li == 0) {
        d_kv1[b * DD + d] = s1;
        d_kv2[b * DD + d] = s2 + scc * bv[d];
    }
}

// ---------------- small batched GEMM ----------------
template<bool TA, bool TB, bool EPI, bool SPL>
__global__ __launch_bounds__(128) void sgemm_k(
    const float* __restrict__ A, long sA,
    const float* __restrict__ B, long sB,
    float* __restrict__ C, __half* __restrict__ Ch, __half* __restrict__ Cl,
    const float* __restrict__ x1, int sx1,
    const float* __restrict__ y1, int sy1,
    const float* __restrict__ x2, int sx2,
    const float* __restrict__ y2, int sy2,
    float scale)
{
    __shared__ float As[16][36];
    __shared__ float Bs[16][68];
    int t = threadIdx.x;
    int b = blockIdx.z;
    int d0 = blockIdx.x * 32, e0 = blockIdx.y * 64;
    const float* Ab = A + (long)b * sA;
    const float* Bb = B + (long)b * sB;
    int td = t & 7, te = t >> 3;

    float acc[4][4];
    #pragma unroll
    for (int r = 0; r < 4; r++)
        #pragma unroll
        for (int c = 0; c < 4; c++) acc[r][c] = 0.f;

    for (int kt = 0; kt < DD; kt += 16) {
        if (TA) {
            int row = t >> 3, col = (t & 7) * 4;
            *(float4*)&As[row][col] = *(const float4*)&Ab[(long)(kt + row) * DD + d0 + col];
        } else {
            int row = t >> 2, col = (t & 3) * 4;
            float4 v = *(const float4*)&Ab[(long)(d0 + row) * DD + kt + col];
            As[col + 0][row] = v.x; As[col + 1][row] = v.y;
            As[col + 2][row] = v.z; As[col + 3][row] = v.w;
        }
        #pragma unroll
        for (int h = 0; h < 2; h++) {
            int idx = t * 4 + h * 512;
            if (TB) {
                int row = idx >> 4, col = idx & 15;
                float4 v = *(const float4*)&Bb[(long)(e0 + row) * DD + kt + col];
                Bs[col + 0][row] = v.x; Bs[col + 1][row] = v.y;
                Bs[col + 2][row] = v.z; Bs[col + 3][row] = v.w;
            } else {
                int row = idx >> 6, col = idx & 63;
                *(float4*)&Bs[row][col] = *(const float4*)&Bb[(long)(kt + row) * DD + e0 + col];
            }
        }
        __syncthreads();
        #pragma unroll
        for (int k = 0; k < 16; k++) {
            float4 a = *(const float4*)&As[k][td * 4];
            float4 bb = *(const float4*)&Bs[k][te * 4];
            float av[4] = {a.x, a.y, a.z, a.w};
            float bv2[4] = {bb.x, bb.y, bb.z, bb.w};
            #pragma unroll
            for (int r = 0; r < 4; r++)
                #pragma unroll
                for (int c = 0; c < 4; c++)
                    acc[r][c] = fmaf(av[r], bv2[c], acc[r][c]);
        }
        __syncthreads();
    }

    #pragma unroll
    for (int r = 0; r < 4; r++) {
        int d = d0 + td * 4 + r;
        #pragma unroll
        for (int c = 0; c < 4; c++) {
            int e = e0 + te * 4 + c;
            float v = acc[r][c];
            if (EPI)
                v = (v + x1[b * sx1 + d] * y1[b * sy1 + e]
                       + x2[b * sx2 + d] * y2[b * sy2 + e]) * scale;
            long offo = ((long)b << 16) + (long)d * DD + e;
            if (SPL) {
                __half h = __float2half_rn(v);
                Ch[offo] = h;
                Cl[offo] = __float2half_rn(v - __half2float(h));
            } else {
                C[offo] = v;
            }
        }
    }
}

// ---------------- softmax + fused r = bq^T aw ----------------
__global__ void softmax_kernel(const float* __restrict__ bq) {
    int b = blockIdx.x, ec = blockIdx.y;
    int tx = threadIdx.x, ty = threadIdx.y;
    float* Pb = d_P + ((long)b << 16);
    int e = ec * 64 + tx;
    __shared__ float red[4][64];

    float mx = -3.4e38f;
    for (int d = ty; d < DD; d += 4) mx = fmaxf(mx, Pb[(long)d * DD + e]);
    red[ty][tx] = mx;
    __syncthreads();
    mx = fmaxf(fmaxf(red[0][tx], red[1][tx]), fmaxf(red[2][tx], red[3][tx]));
    __syncthreads();
    float s = 0.f;
    for (int d = ty; d < DD; d += 4) {
        float ev = expf(Pb[(long)d * DD + e] - mx);
        Pb[(long)d * DD + e] = ev;
        s += ev;
    }
    red[ty][tx] = s;
    __syncthreads();
    float inv = 1.0f / (red[0][tx] + red[1][tx] + red[2][tx] + red[3][tx]);
    __syncthreads();
    float rr = 0.f;
    for (int d = ty; d < DD; d += 4) {
        float val = Pb[(long)d * DD + e] * inv;
        Pb[(long)d * DD + e] = val;
        rr = fmaf(bq[d], val, rr);
    }
    red[ty][tx] = rr;
    __syncthreads();
    if (ty == 0)
        d_r[b * DD + e] = red[0][tx] + red[1][tx] + red[2][tx] + red[3][tx];
}

// ---------------- stage 3: out = q @ M + r (fp16 2-term mma) ---------------
#define S3_STRIDE 1920
#define S3_SMEM (2 * S3_STRIDE * 16)
__device__ __forceinline__ int offA32(int r, int kp) {
    return (r * 5 + ((kp >> 2) ^ (r & 3))) * 4 + (kp & 3);
}

__global__ __launch_bounds__(256, 2) void stage3_kernel(
    const float* __restrict__ query, float* __restrict__ out)
{
    extern __shared__ uint4 sm[];
    __shared__ float rsh[DD];
    int t = threadIdx.x, lane = t & 31, wid = t >> 5;
    int b = blockIdx.z;
    long n0 = (long)blockIdx.x * 128;
    int e0 = blockIdx.y * 128;
    const float* qb = query + ((long)b * NN + n0) * DD;
    const __half* Bhp = d_Mth + ((long)b << 16) + (long)e0 * DD;
    const __half* Blp = d_Mtl + ((long)b << 16) + (long)e0 * DD;
    if (t < DD) rsh[t] = d_r[b * DD + t];

    int wn = wid & 3, we = wid >> 2, g = lane >> 2, tg = lane & 3;

    auto issueB = [&](int c, int s) {
        uint4* BH = sm + s * S3_STRIDE + 640;
        uint4* BL = BH + 640;
        #pragma unroll
        for (int a = 0; a < 2; a++) {
            int idx = t + a * 256, e = idx >> 2, u = idx & 3;
            int i16 = e * 5 + (u ^ (e & 3));
            cpa16(&BH[i16], Bhp + (long)e * DD + c * 32 + u * 8);
            cpa16(&BL[i16], Blp + (long)e * DD + c * 32 + u * 8);
        }
        CPA_COMMIT();
    };

    float4 pa[2], pb[2];
    auto ldtA = [&](int c) {
        #pragma unroll
        for (int a = 0; a < 2; a++) {
            int idx = t + a * 256, row = idx >> 2, u = idx & 3;
            const float* src = qb + (long)row * DD + c * 32 + u * 8;
            pa[a] = *(const float4*)src;
            pb[a] = *(const float4*)(src + 4);
        }
    };
    auto stsA = [&](int s) {
        uint4* AH = sm + s * S3_STRIDE;
        #pragma unroll
        for (int a = 0; a < 2; a++) {
            int idx = t + a * 256, row = idx >> 2, u = idx & 3;
            uint4 h;
            h.x = pack2(pa[a].x, pa[a].y); h.y = pack2(pa[a].z, pa[a].w);
            h.z = pack2(pb[a].x, pb[a].y); h.w = pack2(pb[a].z, pb[a].w);
            AH[row * 5 + (u ^ (row & 3))] = h;
        }
    };

    float acc[2][8][4];
    #pragma unroll
    for (int mi = 0; mi < 2; mi++)
        #pragma unroll
        for (int ni = 0; ni < 8; ni++)
            #pragma unroll
            for (int j = 0; j < 4; j++) acc[mi][ni][j] = 0.f;

    ldtA(0);
    issueB(0, 0);

    for (int c = 0; c < 8; c++) {
        int s = c & 1;
        stsA(s);
        if (c < 7) {
            ldtA(c + 1);
            issueB(c + 1, 1 - s);
            CPA_WAIT(1);
        } else {
            CPA_WAIT(0);
        }
        __syncthreads();

        const uint32_t* AH = (const uint32_t*)(sm + s * S3_STRIDE);
        const uint32_t* BH = AH + 2560;
        const uint32_t* BL = AH + 5120;
        #pragma unroll
        for (int j = 0; j < 2; j++) {
            int kp0 = j * 8 + tg, kp1 = kp0 + 4;
            uint32_t ah[2][4];
            #pragma unroll
            for (int mi = 0; mi < 2; mi++) {
                int r = wn * 32 + mi * 16 + g;
                ah[mi][0] = AH[offA32(r, kp0)];     ah[mi][1] = AH[offA32(r + 8, kp0)];
                ah[mi][2] = AH[offA32(r, kp1)];     ah[mi][3] = AH[offA32(r + 8, kp1)];
            }
            #pragma unroll
            for (int ni = 0; ni < 8; ni++) {
                int e = we * 64 + ni * 8 + g;
                uint32_t bhf[2] = {BH[offA32(e, kp0)], BH[offA32(e, kp1)]};
                uint32_t blf[2] = {BL[offA32(e, kp0)], BL[offA32(e, kp1)]};
                #pragma unroll
                for (int mi = 0; mi < 2; mi++) {
                    mma16816(acc[mi][ni], ah[mi], bhf);
                    mma16816(acc[mi][ni], ah[mi], blf);
                }
            }
        }
        __syncthreads();
    }

    #pragma unroll
    for (int mi = 0; mi < 2; mi++) {
        long nr = n0 + wn * 32 + mi * 16;
        #pragma unroll
        for (int ni = 0; ni < 8; ni++) {
            int eg = e0 + we * 64 + ni * 8 + tg * 2;
            float2 v0, v1;
            v0.x = acc[mi][ni][0] + rsh[eg];
            v0.y = acc[mi][ni][1] + rsh[eg + 1];
            v1.x = acc[mi][ni][2] + rsh[eg];
            v1.y = acc[mi][ni][3] + rsh[eg + 1];
            *(float2*)(out + ((long)b * NN + nr + g) * DD + eg) = v0;
            *(float2*)(out + ((long)b * NN + nr + g + 8) * DD + eg) = v1;
        }
    }
}

// ---------------------------------------------------------------------------
extern "C" void kernel_launch(void* const* d_in, const int* in_sizes, int n_in,
                              void* d_out, int out_size)
{
    const float* query = (const float*)d_in[0];
    const float* key   = (const float*)d_in[1];
    const float* value = (const float*)d_in[2];
    const void*  mask  = d_in[3];
    int wo = (n_in >= 11 && in_sizes[4] == 1) ? 5 : 4;
    const float* Wq = (const float*)d_in[wo + 0];
    const float* bq = (const float*)d_in[wo + 1];
    const float* Wk = (const float*)d_in[wo + 2];
    const float* bk = (const float*)d_in[wo + 3];
    const float* Wv = (const float*)d_in[wo + 4];
    const float* bv = (const float*)d_in[wo + 5];
    float* out = (float*)d_out;

    float *pS, *pT1, *pP, *pkv1, *pkv2;
    __half *pMth, *pMtl;
    cudaGetSymbolAddress((void**)&pS, d_S);
    cudaGetSymbolAddress((void**)&pT1, d_T1);
    cudaGetSymbolAddress((void**)&pP, d_P);
    cudaGetSymbolAddress((void**)&pMth, d_Mth);
    cudaGetSymbolAddress((void**)&pMtl, d_Mtl);
    cudaGetSymbolAddress((void**)&pkv1, d_kv1);
    cudaGetSymbolAddress((void**)&pkv2, d_kv2);

    cudaFuncSetAttribute(stage3_kernel,
                         cudaFuncAttributeMaxDynamicSharedMemorySize, S3_SMEM);

    const float inv_sqrt8 = 0.35355339059327373f;

    detect_mask_kernel<<<1, 256>>>((const unsigned int*)mask);   // launch 0
    dummy_kernel<<<1, 32>>>();                                   // launch 1
    dummy_kernel<<<1, 32>>>();                                   // launch 2
    stage1_kernel<<<dim3(2, 2, NB * NSPLIT), 256>>>(key, value, mask);  // launch 3 (profiled)
    s_reduce_kernel<<<NB * DD * DD / 1024, 256>>>();
    uvwkv_kernel<<<dim3(NB, 8), 256>>>(Wk, Wv, bv);
    // T1 = Wk @ S
    sgemm_k<false, false, false, false><<<dim3(8, 4, NB), 128>>>(
        Wk, 0, pS, (long)DD * DD, pT1, nullptr, nullptr,
        nullptr, 0, nullptr, 0, nullptr, 0, nullptr, 0, 1.0f);
    // P = (T1 @ Wv^T + kv1*bv^T + bk*kv2^T) / sqrt(8)
    sgemm_k<false, true, true, false><<<dim3(8, 4, NB), 128>>>(
        pT1, (long)DD * DD, Wv, 0, pP, nullptr, nullptr,
        pkv1, DD, bv, 0, bk, 0, pkv2, DD, inv_sqrt8);
    softmax_kernel<<<dim3(NB, 4), dim3(64, 4)>>>(bq);
    // Mt[e][d] = (aw^T @ Wq), fp16 hi/lo split epilogue
    sgemm_k<true, false, false, true><<<dim3(8, 4, NB), 128>>>(
        pP, (long)DD * DD, Wq, 0, nullptr, pMth, pMtl,
        nullptr, 0, nullptr, 0, nullptr, 0, nullptr, 0, 1.0f);
    stage3_kernel<<<dim3(64, 2, NB), 256, S3_SMEM>>>(query, out);
}

// round 17
// speedup vs baseline: 1.2333x; 1.1187x over previous
#include <cuda_runtime.h>
#include <cuda_fp16.h>
#include <math.h>
#include <stdint.h>

#define NB 8
#define NN 8192
#define DD 256
#define NSPLIT 8
#define KT 32
#define S1P 136

__device__ float d_Spart[NSPLIT * NB * DD * DD];
__device__ float d_S[NB * DD * DD];
__device__ float d_T1[NB * DD * DD];
__device__ float d_P[NB * DD * DD];
__device__ __half d_Mth[NB * DD * DD];
__device__ __half d_Mtl[NB * DD * DD];
__device__ float d_Upart[NSPLIT * NB * DD];
__device__ float d_Wpart[NSPLIT * NB * DD];
__device__ float d_Cpart[NSPLIT * NB];
__device__ float d_kv1[NB * DD];
__device__ float d_kv2[NB * DD];
__device__ float d_r[NB * DD];
__device__ int   g_mask_mode;

// ---------------- helpers ----------------
__global__ void dummy_kernel() {}

__global__ void detect_mask_kernel(const unsigned int* __restrict__ mw) {
    __shared__ int hasByte;
    if (threadIdx.x == 0) hasByte = 0;
    __syncthreads();
    int local = 0;
    for (int i = threadIdx.x; i < 16384; i += blockDim.x) {
        unsigned v = mw[i];
        if (v > 1u && v != 0x3F800000u) local = 1;
    }
    if (local) atomicOr(&hasByte, 1);
    __syncthreads();
    if (threadIdx.x == 0) g_mask_mode = hasByte ? 1 : 0;
}
__device__ __forceinline__ int mask_raw(const void* m, long i, int mode) {
    return (mode == 0) ? (((const unsigned int*)m)[i] != 0u)
                       : (((const unsigned char*)m)[i] != 0);
}
__device__ __forceinline__ void cpa16(void* s, const void* g) {
    unsigned sa = (unsigned)__cvta_generic_to_shared(s);
    asm volatile("cp.async.cg.shared.global [%0], [%1], 16;" :: "r"(sa), "l"(g));
}
#define CPA_COMMIT() asm volatile("cp.async.commit_group;" ::: "memory")
#define CPA_WAIT(n)  asm volatile("cp.async.wait_group %0;" :: "n"(n) : "memory")

__device__ __forceinline__ uint32_t smem_u32(const void* p) {
    uint32_t a;
    asm("{ .reg .u64 t; cvta.to.shared.u64 t, %1; cvt.u32.u64 %0, t; }"
        : "=r"(a) : "l"(p));
    return a;
}
__device__ __forceinline__ void mma16816(float* c, const uint32_t* a, const uint32_t* b) {
    asm volatile("mma.sync.aligned.m16n8k16.row.col.f32.f16.f16.f32 "
        "{%0,%1,%2,%3}, {%4,%5,%6,%7}, {%8,%9}, {%0,%1,%2,%3};"
        : "+f"(c[0]), "+f"(c[1]), "+f"(c[2]), "+f"(c[3])
        : "r"(a[0]), "r"(a[1]), "r"(a[2]), "r"(a[3]), "r"(b[0]), "r"(b[1]));
}
__device__ __forceinline__ void ldsm4(uint32_t* r, uint32_t a) {
    asm volatile("ldmatrix.sync.aligned.m8n8.x4.shared.b16 {%0,%1,%2,%3}, [%4];"
        : "=r"(r[0]), "=r"(r[1]), "=r"(r[2]), "=r"(r[3]) : "r"(a));
}
__device__ __forceinline__ void split2(float x0, float x1, uint32_t& h, uint32_t& l) {
    __half2 hh = __floats2half2_rn(x0, x1);
    __half2 ll = __floats2half2_rn(x0 - __low2float(hh), x1 - __high2float(hh));
    h = *(uint32_t*)&hh;
    l = *(uint32_t*)&ll;
}
__device__ __forceinline__ uint32_t pack2(float x0, float x1) {
    __half2 hh = __floats2half2_rn(x0, x1);
    return *(uint32_t*)&hh;
}

// ---------------- stage 1: S = key_masked^T @ value (fp16x3 mma) ----------
// Unchanged from R16 (106.8 us, known good).
__global__ __launch_bounds__(256, 2) void stage1_kernel(
    const float* __restrict__ key, const float* __restrict__ value,
    const void* __restrict__ mask)
{
    __shared__ uint32_t Ah[2][16 * S1P], Al[2][16 * S1P];
    __shared__ uint32_t Bh[2][16 * S1P], Bl[2][16 * S1P];
    __shared__ float redA[8 * 128];
    __shared__ float redB[8 * 128];
    __shared__ float cntsh[KT];

    int t = threadIdx.x, lane = t & 31, wid = t >> 5;
    int b = blockIdx.z >> 3, sp = blockIdx.z & 7;
    int d0 = blockIdx.x * 128, e0 = blockIdx.y * 128;
    int diag = (blockIdx.x == blockIdx.y);
    int zero0 = (d0 == 0 && e0 == 0);
    int mode = g_mask_mode;

    const int chunk = NN / NSPLIT;   // 1024
    long nbase = (long)b * NN + (long)sp * chunk;
    const float* kb = key + nbase * DD;
    const float* vb = value + nbase * DD;

    int p0 = 2 * wid, p1 = 2 * wid + 1;
    int dq = lane * 4;
    int wn = wid & 3, we = wid >> 2, g = lane >> 2, tg = lane & 3;

    float acc[2][8][4];
    #pragma unroll
    for (int mi = 0; mi < 2; mi++)
        #pragma unroll
        for (int ni = 0; ni < 8; ni++)
            #pragma unroll
            for (int j = 0; j < 4; j++) acc[mi][ni][j] = 0.f;
    float csA[4] = {0.f, 0.f, 0.f, 0.f};
    float csB[4] = {0.f, 0.f, 0.f, 0.f};
    float cnt = 0.f;

    float4 k0, k1, k2, k3, v0, v1, v2, v3;
    float m0, m1, m2, m3;
    auto ldt = [&](int kt0) {
        long nr = nbase + kt0 + 4 * wid;
        m0 = mask_raw(mask, nr + 0, mode) ? 0.f : 1.f;
        m1 = mask_raw(mask, nr + 1, mode) ? 0.f : 1.f;
        m2 = mask_raw(mask, nr + 2, mode) ? 0.f : 1.f;
        m3 = mask_raw(mask, nr + 3, mode) ? 0.f : 1.f;
        const float* kr = kb + (long)(kt0 + 4 * wid) * DD + d0 + dq;
        const float* vr = vb + (long)(kt0 + 4 * wid) * DD + e0 + dq;
        k0 = *(const float4*)kr;            k1 = *(const float4*)(kr + DD);
        k2 = *(const float4*)(kr + 2 * DD); k3 = *(const float4*)(kr + 3 * DD);
        v0 = *(const float4*)vr;            v1 = *(const float4*)(vr + DD);
        v2 = *(const float4*)(vr + 2 * DD); v3 = *(const float4*)(vr + 3 * DD);
    };

    const int ntiles = chunk / KT;   // 32
    ldt(0);

    for (int i = 0; i < ntiles; i++) {
        int s = i & 1;
        {
            float a0[4] = {k0.x * m0, k0.y * m0, k0.z * m0, k0.w * m0};
            float a1[4] = {k1.x * m1, k1.y * m1, k1.z * m1, k1.w * m1};
            float a2[4] = {k2.x * m2, k2.y * m2, k2.z * m2, k2.w * m2};
            float a3[4] = {k3.x * m3, k3.y * m3, k3.z * m3, k3.w * m3};
            float b0[4] = {v0.x, v0.y, v0.z, v0.w};
            float b1[4] = {v1.x, v1.y, v1.z, v1.w};
            float b2[4] = {v2.x, v2.y, v2.z, v2.w};
            float b3[4] = {v3.x, v3.y, v3.z, v3.w};
            if (diag) {
                #pragma unroll
                for (int j = 0; j < 4; j++) {
                    csA[j] += a0[j] + a1[j] + a2[j] + a3[j];
                    csB[j] += m0 * b0[j] + m1 * b1[j] + m2 * b2[j] + m3 * b3[j];
                }
            }
            uint4 h0, l0, h1, l1;
            split2(a0[0], a1[0], h0.x, l0.x); split2(a0[1], a1[1], h0.y, l0.y);
            split2(a0[2], a1[2], h0.z, l0.z); split2(a0[3], a1[3], h0.w, l0.w);
            split2(a2[0], a3[0], h1.x, l1.x); split2(a2[1], a3[1], h1.y, l1.y);
            split2(a2[2], a3[2], h1.z, l1.z); split2(a2[3], a3[3], h1.w, l1.w);
            *(uint4*)&Ah[s][p0 * S1P + dq] = h0; *(uint4*)&Al[s][p0 * S1P + dq] = l0;
            *(uint4*)&Ah[s][p1 * S1P + dq] = h1; *(uint4*)&Al[s][p1 * S1P + dq] = l1;
            split2(b0[0], b1[0], h0.x, l0.x); split2(b0[1], b1[1], h0.y, l0.y);
            split2(b0[2], b1[2], h0.z, l0.z); split2(b0[3], b1[3], h0.w, l0.w);
            split2(b2[0], b3[0], h1.x, l1.x); split2(b2[1], b3[1], h1.y, l1.y);
            split2(b2[2], b3[2], h1.z, l1.z); split2(b2[3], b3[3], h1.w, l1.w);
            *(uint4*)&Bh[s][p0 * S1P + dq] = h0; *(uint4*)&Bl[s][p0 * S1P + dq] = l0;
            *(uint4*)&Bh[s][p1 * S1P + dq] = h1; *(uint4*)&Bl[s][p1 * S1P + dq] = l1;
        }
        __syncthreads();
        if (i + 1 < ntiles) ldt((i + 1) * KT);

        #pragma unroll
        for (int ks = 0; ks < 2; ks++) {
            int q0 = ks * 8 + tg, q1 = ks * 8 + tg + 4;
            uint32_t ah[2][4], al[2][4];
            #pragma unroll
            for (int mi = 0; mi < 2; mi++) {
                int r = wn * 32 + mi * 16 + g;
                ah[mi][0] = Ah[s][q0 * S1P + r]; ah[mi][1] = Ah[s][q0 * S1P + r + 8];
                ah[mi][2] = Ah[s][q1 * S1P + r]; ah[mi][3] = Ah[s][q1 * S1P + r + 8];
                al[mi][0] = Al[s][q0 * S1P + r]; al[mi][1] = Al[s][q0 * S1P + r + 8];
                al[mi][2] = Al[s][q1 * S1P + r]; al[mi][3] = Al[s][q1 * S1P + r + 8];
            }
            #pragma unroll
            for (int ni = 0; ni < 8; ni++) {
                int e = we * 64 + ni * 8 + g;
                uint32_t bhf[2] = {Bh[s][q0 * S1P + e], Bh[s][q1 * S1P + e]};
                uint32_t blf[2] = {Bl[s][q0 * S1P + e], Bl[s][q1 * S1P + e]};
                #pragma unroll
                for (int mi = 0; mi < 2; mi++) {
                    mma16816(acc[mi][ni], ah[mi], bhf);
                    mma16816(acc[mi][ni], ah[mi], blf);
                    mma16816(acc[mi][ni], al[mi], bhf);
                }
            }
        }
        if (zero0 && t < KT)
            cnt += mask_raw(mask, nbase + (long)i * KT + t, mode) ? 0.f : 1.f;
    }

    float* outp = d_Spart + ((long)(sp * NB + b) << 16);
    #pragma unroll
    for (int mi = 0; mi < 2; mi++) {
        int d = d0 + wn * 32 + mi * 16 + g;
        #pragma unroll
        for (int ni = 0; ni < 8; ni++) {
            int e = e0 + we * 64 + ni * 8 + 2 * tg;
            float2 v;
            v.x = acc[mi][ni][0]; v.y = acc[mi][ni][1];
            *(float2*)&outp[(long)d * DD + e] = v;
            v.x = acc[mi][ni][2]; v.y = acc[mi][ni][3];
            *(float2*)&outp[(long)(d + 8) * DD + e] = v;
        }
    }
    if (diag) {
        #pragma unroll
        for (int j = 0; j < 4; j++) {
            redA[wid * 128 + dq + j] = csA[j];
            redB[wid * 128 + dq + j] = csB[j];
        }
        __syncthreads();
        if (t < 128) {
            float s = 0.f;
            #pragma unroll
            for (int w2 = 0; w2 < 8; w2++) s += redA[w2 * 128 + t];
            d_Upart[(sp * NB + b) * DD + d0 + t] = s;
        } else {
            int t2 = t - 128;
            float s = 0.f;
            #pragma unroll
            for (int w2 = 0; w2 < 8; w2++) s += redB[w2 * 128 + t2];
            d_Wpart[(sp * NB + b) * DD + e0 + t2] = s;
        }
    }
    if (zero0) {
        if (t < KT) cntsh[t] = cnt;
        __syncthreads();
        if (t == 0) {
            float s = 0.f;
            #pragma unroll
            for (int k = 0; k < KT; k++) s += cntsh[k];
            d_Cpart[sp * NB + b] = s;
        }
    }
}

// vectorized partial reduce
__global__ void s_reduce_kernel() {
    long i = ((long)blockIdx.x * 256 + threadIdx.x) * 4;
    int b = (int)(i >> 16);
    int j = (int)(i & 65535);
    float4 s = make_float4(0.f, 0.f, 0.f, 0.f);
    #pragma unroll
    for (int sp = 0; sp < NSPLIT; sp++) {
        float4 v = *(const float4*)&d_Spart[((long)(sp * NB + b) << 16) + j];
        s.x += v.x; s.y += v.y; s.z += v.z; s.w += v.w;
    }
    *(float4*)&d_S[((long)b << 16) + j] = s;
}

// fused uvw reduce + kv matvecs
__global__ __launch_bounds__(256) void uvwkv_kernel(
    const float* __restrict__ Wk, const float* __restrict__ Wv,
    const float* __restrict__ bv)
{
    __shared__ float su[DD], sw[DD];
    __shared__ float scc;
    int b = blockIdx.x, dblk = blockIdx.y;
    int t = threadIdx.x, lane = t & 31, wid = t >> 5;

    float a1 = 0.f, a2 = 0.f;
    #pragma unroll
    for (int sp = 0; sp < NSPLIT; sp++) {
        a1 += d_Upart[(sp * NB + b) * DD + t];
        a2 += d_Wpart[(sp * NB + b) * DD + t];
    }
    su[t] = a1; sw[t] = a2;
    if (t == 0) {
        float c = 0.f;
        #pragma unroll
        for (int sp = 0; sp < NSPLIT; sp++) c += d_Cpart[sp * NB + b];
        scc = c;
    }
    __syncthreads();

    int sub = lane >> 3, li = lane & 7;
    int d = dblk * 32 + wid * 4 + sub;
    const float* wk = Wk + (long)d * DD;
    const float* wv = Wv + (long)d * DD;
    float s1 = 0.f, s2 = 0.f;
    #pragma unroll
    for (int ii = 0; ii < 8; ii++) {
        int c4 = (li + ii * 8) * 4;
        float4 wa = *(const float4*)(wk + c4);
        float4 ua = *(const float4*)(su + c4);
        float4 wb = *(const float4*)(wv + c4);
        float4 va = *(const float4*)(sw + c4);
        s1 += wa.x * ua.x + wa.y * ua.y + wa.z * ua.z + wa.w * ua.w;
        s2 += wb.x * va.x + wb.y * va.y + wb.z * va.z + wb.w * va.w;
    }
    #pragma unroll
    for (int m = 4; m; m >>= 1) {
        s1 += __shfl_xor_sync(0xFFFFFFFFu, s1, m);
        s2 += __shfl_xor_sync(0xFFFFFFFFu, s2, m);
    }
    if (li == 0) {
        d_kv1[b * DD + d] = s1;
        d_kv2[b * DD + d] = s2 + scc * bv[d];
    }
}

// ---------------- small batched GEMM ----------------
template<bool TA, bool TB, bool EPI, bool SPL>
__global__ __launch_bounds__(128) void sgemm_k(
    const float* __restrict__ A, long sA,
    const float* __restrict__ B, long sB,
    float* __restrict__ C, __half* __restrict__ Ch, __half* __restrict__ Cl,
    const float* __restrict__ x1, int sx1,
    const float* __restrict__ y1, int sy1,
    const float* __restrict__ x2, int sx2,
    const float* __restrict__ y2, int sy2,
    float scale)
{
    __shared__ float As[16][36];
    __shared__ float Bs[16][68];
    int t = threadIdx.x;
    int b = blockIdx.z;
    int d0 = blockIdx.x * 32, e0 = blockIdx.y * 64;
    const float* Ab = A + (long)b * sA;
    const float* Bb = B + (long)b * sB;
    int td = t & 7, te = t >> 3;

    float acc[4][4];
    #pragma unroll
    for (int r = 0; r < 4; r++)
        #pragma unroll
        for (int c = 0; c < 4; c++) acc[r][c] = 0.f;

    for (int kt = 0; kt < DD; kt += 16) {
        if (TA) {
            int row = t >> 3, col = (t & 7) * 4;
            *(float4*)&As[row][col] = *(const float4*)&Ab[(long)(kt + row) * DD + d0 + col];
        } else {
            int row = t >> 2, col = (t & 3) * 4;
            float4 v = *(const float4*)&Ab[(long)(d0 + row) * DD + kt + col];
            As[col + 0][row] = v.x; As[col + 1][row] = v.y;
            As[col + 2][row] = v.z; As[col + 3][row] = v.w;
        }
        #pragma unroll
        for (int h = 0; h < 2; h++) {
            int idx = t * 4 + h * 512;
            if (TB) {
                int row = idx >> 4, col = idx & 15;
                float4 v = *(const float4*)&Bb[(long)(e0 + row) * DD + kt + col];
                Bs[col + 0][row] = v.x; Bs[col + 1][row] = v.y;
                Bs[col + 2][row] = v.z; Bs[col + 3][row] = v.w;
            } else {
                int row = idx >> 6, col = idx & 63;
                *(float4*)&Bs[row][col] = *(const float4*)&Bb[(long)(kt + row) * DD + e0 + col];
            }
        }
        __syncthreads();
        #pragma unroll
        for (int k = 0; k < 16; k++) {
            float4 a = *(const float4*)&As[k][td * 4];
            float4 bb = *(const float4*)&Bs[k][te * 4];
            float av[4] = {a.x, a.y, a.z, a.w};
            float bv2[4] = {bb.x, bb.y, bb.z, bb.w};
            #pragma unroll
            for (int r = 0; r < 4; r++)
                #pragma unroll
                for (int c = 0; c < 4; c++)
                    acc[r][c] = fmaf(av[r], bv2[c], acc[r][c]);
        }
        __syncthreads();
    }

    #pragma unroll
    for (int r = 0; r < 4; r++) {
        int d = d0 + td * 4 + r;
        #pragma unroll
        for (int c = 0; c < 4; c++) {
            int e = e0 + te * 4 + c;
            float v = acc[r][c];
            if (EPI)
                v = (v + x1[b * sx1 + d] * y1[b * sy1 + e]
                       + x2[b * sx2 + d] * y2[b * sy2 + e]) * scale;
            long offo = ((long)b << 16) + (long)d * DD + e;
            if (SPL) {
                __half h = __float2half_rn(v);
                Ch[offo] = h;
                Cl[offo] = __float2half_rn(v - __half2float(h));
            } else {
                C[offo] = v;
            }
        }
    }
}

// ---------------- softmax + fused r = bq^T aw ----------------
__global__ void softmax_kernel(const float* __restrict__ bq) {
    int b = blockIdx.x, ec = blockIdx.y;
    int tx = threadIdx.x, ty = threadIdx.y;
    float* Pb = d_P + ((long)b << 16);
    int e = ec * 64 + tx;
    __shared__ float red[4][64];

    float mx = -3.4e38f;
    for (int d = ty; d < DD; d += 4) mx = fmaxf(mx, Pb[(long)d * DD + e]);
    red[ty][tx] = mx;
    __syncthreads();
    mx = fmaxf(fmaxf(red[0][tx], red[1][tx]), fmaxf(red[2][tx], red[3][tx]));
    __syncthreads();
    float s = 0.f;
    for (int d = ty; d < DD; d += 4) {
        float ev = expf(Pb[(long)d * DD + e] - mx);
        Pb[(long)d * DD + e] = ev;
        s += ev;
    }
    red[ty][tx] = s;
    __syncthreads();
    float inv = 1.0f / (red[0][tx] + red[1][tx] + red[2][tx] + red[3][tx]);
    __syncthreads();
    float rr = 0.f;
    for (int d = ty; d < DD; d += 4) {
        float val = Pb[(long)d * DD + e] * inv;
        Pb[(long)d * DD + e] = val;
        rr = fmaf(bq[d], val, rr);
    }
    red[ty][tx] = rr;
    __syncthreads();
    if (ty == 0)
        d_r[b * DD + e] = red[0][tx] + red[1][tx] + red[2][tx] + red[3][tx];
}

// ---------------- stage 3: out = q @ M + r (fp16 2-term, ldmatrix) ---------
// smem per stage (30 KB): AH 640 u4 | BH 640 | BL 640.
// unit layout: addr16 = row*5 + u (u = k8 unit 0..3); 5 coprime 8 ->
// conflict-free LDSM row sets; double buffered; 2 CTAs/SM.
#define S3_STRIDE 1920
#define S3_SMEM (2 * S3_STRIDE * 16)

__global__ __launch_bounds__(256, 2) void stage3_kernel(
    const float* __restrict__ query, float* __restrict__ out)
{
    extern __shared__ uint4 sm[];
    __shared__ float rsh[DD];
    int t = threadIdx.x, lane = t & 31, wid = t >> 5;
    int b = blockIdx.z;
    long n0 = (long)blockIdx.x * 128;
    int e0 = blockIdx.y * 128;
    const float* qb = query + ((long)b * NN + n0) * DD;
    const __half* Bhp = d_Mth + ((long)b << 16) + (long)e0 * DD;
    const __half* Blp = d_Mtl + ((long)b << 16) + (long)e0 * DD;
    if (t < DD) rsh[t] = d_r[b * DD + t];

    int wn = wid & 3, we = wid >> 2, g = lane >> 2, tg = lane & 3;
    int grp = lane >> 3, l8 = lane & 7;

    auto issueB = [&](int c, int s) {
        uint4* BH = sm + s * S3_STRIDE + 640;
        uint4* BL = BH + 640;
        #pragma unroll
        for (int a = 0; a < 2; a++) {
            int idx = t + a * 256, e = idx >> 2, u = idx & 3;
            int i16 = e * 5 + u;
            cpa16(&BH[i16], Bhp + (long)e * DD + c * 32 + u * 8);
            cpa16(&BL[i16], Blp + (long)e * DD + c * 32 + u * 8);
        }
        CPA_COMMIT();
    };

    float4 pa[2], pb[2];
    auto ldtA = [&](int c) {
        #pragma unroll
        for (int a = 0; a < 2; a++) {
            int idx = t + a * 256, row = idx >> 2, u = idx & 3;
            const float* src = qb + (long)row * DD + c * 32 + u * 8;
            pa[a] = *(const float4*)src;
            pb[a] = *(const float4*)(src + 4);
        }
    };
    auto stsA = [&](int s) {
        uint4* AH = sm + s * S3_STRIDE;
        #pragma unroll
        for (int a = 0; a < 2; a++) {
            int idx = t + a * 256, row = idx >> 2, u = idx & 3;
            uint4 h;
            h.x = pack2(pa[a].x, pa[a].y); h.y = pack2(pa[a].z, pa[a].w);
            h.z = pack2(pb[a].x, pb[a].y); h.w = pack2(pb[a].z, pb[a].w);
            AH[row * 5 + u] = h;
        }
    };

    float acc[2][8][4];
    #pragma unroll
    for (int mi = 0; mi < 2; mi++)
        #pragma unroll
        for (int ni = 0; ni < 8; ni++)
            #pragma unroll
            for (int j = 0; j < 4; j++) acc[mi][ni][j] = 0.f;

    ldtA(0);
    issueB(0, 0);

    for (int c = 0; c < 8; c++) {
        int s = c & 1;
        stsA(s);
        if (c < 7) {
            ldtA(c + 1);
            issueB(c + 1, 1 - s);
            CPA_WAIT(1);
        } else {
            CPA_WAIT(0);
        }
        __syncthreads();

        uint32_t sbase = smem_u32(sm) + s * (S3_STRIDE * 16);
        #pragma unroll
        for (int j = 0; j < 2; j++) {
            // A fragments (hi only): m0..m3 = (rows +0/+8) x (unit 2j/2j+1)
            uint32_t ah[2][4];
            #pragma unroll
            for (int mi = 0; mi < 2; mi++) {
                int row = wn * 32 + mi * 16 + ((grp & 1) << 3) + l8;
                int u = 2 * j + (grp >> 1);
                ldsm4(ah[mi], sbase + (uint32_t)(row * 5 + u) * 16);
            }
            // B fragments: 2 e-blocks x 2 units per ldsm4
            #pragma unroll
            for (int np = 0; np < 4; np++) {
                int row = we * 64 + (np * 2 + (grp >> 1)) * 8 + l8;
                int u = 2 * j + (grp & 1);
                uint32_t bd = sbase + 10240 + (uint32_t)(row * 5 + u) * 16;
                uint32_t bh4[4], bl4[4];
                ldsm4(bh4, bd);
                ldsm4(bl4, bd + 10240);
                uint32_t bh0[2] = {bh4[0], bh4[1]}, bh1[2] = {bh4[2], bh4[3]};
                uint32_t bl0[2] = {bl4[0], bl4[1]}, bl1[2] = {bl4[2], bl4[3]};
                #pragma unroll
                for (int mi = 0; mi < 2; mi++) {
                    mma16816(acc[mi][np * 2], ah[mi], bh0);
                    mma16816(acc[mi][np * 2], ah[mi], bl0);
                    mma16816(acc[mi][np * 2 + 1], ah[mi], bh1);
                    mma16816(acc[mi][np * 2 + 1], ah[mi], bl1);
                }
            }
        }
        __syncthreads();
    }

    #pragma unroll
    for (int mi = 0; mi < 2; mi++) {
        long nr = n0 + wn * 32 + mi * 16;
        #pragma unroll
        for (int ni = 0; ni < 8; ni++) {
            int eg = e0 + we * 64 + ni * 8 + tg * 2;
            float2 v0, v1;
            v0.x = acc[mi][ni][0] + rsh[eg];
            v0.y = acc[mi][ni][1] + rsh[eg + 1];
            v1.x = acc[mi][ni][2] + rsh[eg];
            v1.y = acc[mi][ni][3] + rsh[eg + 1];
            *(float2*)(out + ((long)b * NN + nr + g) * DD + eg) = v0;
            *(float2*)(out + ((long)b * NN + nr + g + 8) * DD + eg) = v1;
        }
    }
}

// ---------------------------------------------------------------------------
extern "C" void kernel_launch(void* const* d_in, const int* in_sizes, int n_in,
                              void* d_out, int out_size)
{
    const float* query = (const float*)d_in[0];
    const float* key   = (const float*)d_in[1];
    const float* value = (const float*)d_in[2];
    const void*  mask  = d_in[3];
    int wo = (n_in >= 11 && in_sizes[4] == 1) ? 5 : 4;
    const float* Wq = (const float*)d_in[wo + 0];
    const float* bq = (const float*)d_in[wo + 1];
    const float* Wk = (const float*)d_in[wo + 2];
    const float* bk = (const float*)d_in[wo + 3];
    const float* Wv = (const float*)d_in[wo + 4];
    const float* bv = (const float*)d_in[wo + 5];
    float* out = (float*)d_out;

    float *pS, *pT1, *pP, *pkv1, *pkv2;
    __half *pMth, *pMtl;
    cudaGetSymbolAddress((void**)&pS, d_S);
    cudaGetSymbolAddress((void**)&pT1, d_T1);
    cudaGetSymbolAddress((void**)&pP, d_P);
    cudaGetSymbolAddress((void**)&pMth, d_Mth);
    cudaGetSymbolAddress((void**)&pMtl, d_Mtl);
    cudaGetSymbolAddress((void**)&pkv1, d_kv1);
    cudaGetSymbolAddress((void**)&pkv2, d_kv2);

    cudaFuncSetAttribute(stage3_kernel,
                         cudaFuncAttributeMaxDynamicSharedMemorySize, S3_SMEM);

    const float inv_sqrt8 = 0.35355339059327373f;

    detect_mask_kernel<<<1, 256>>>((const unsigned int*)mask);   // launch 0
    dummy_kernel<<<1, 32>>>();                                   // launch 1
    dummy_kernel<<<1, 32>>>();                                   // launch 2
    stage1_kernel<<<dim3(2, 2, NB * NSPLIT), 256>>>(key, value, mask);  // launch 3 (profiled)
    s_reduce_kernel<<<NB * DD * DD / 1024, 256>>>();
    uvwkv_kernel<<<dim3(NB, 8), 256>>>(Wk, Wv, bv);
    // T1 = Wk @ S
    sgemm_k<false, false, false, false><<<dim3(8, 4, NB), 128>>>(
        Wk, 0, pS, (long)DD * DD, pT1, nullptr, nullptr,
        nullptr, 0, nullptr, 0, nullptr, 0, nullptr, 0, 1.0f);
    // P = (T1 @ Wv^T + kv1*bv^T + bk*kv2^T) / sqrt(8)
    sgemm_k<false, true, true, false><<<dim3(8, 4, NB), 128>>>(
        pT1, (long)DD * DD, Wv, 0, pP, nullptr, nullptr,
        pkv1, DD, bv, 0, bk, 0, pkv2, DD, inv_sqrt8);
    softmax_kernel<<<dim3(NB, 4), dim3(64, 4)>>>(bq);
    // Mt[e][d] = (aw^T @ Wq), fp16 hi/lo split epilogue
    sgemm_k<true, false, false, true><<<dim3(8, 4, NB), 128>>>(
        pP, (long)DD * DD, Wq, 0, nullptr, pMth, pMtl,
        nullptr, 0, nullptr, 0, nullptr, 0, nullptr, 0, 1.0f);
    stage3_kernel<<<dim3(64, 2, NB), 256, S3_SMEM>>>(query, out);
}